// round 1
// baseline (speedup 1.0000x reference)
#include <cuda_runtime.h>
#include <cuda_bf16.h>
#include <cstdint>

// ---------------------------------------------------------------------------
// SageConv link predictor, restructured:
//   y = x @ [W1l | W1r]                         (one fp32 GEMM, [N,256])
//   per node i: h_i = relu(mean_{j->i} y_j[0:128] + y_i[128:256] + b1)
//               sab_i = (h_i . avec, h_i . bvec)      (avec = W2l @ wA, ...)
//               scd_i = (h_i . cvec + kA, h_i . dvec + kB)
//   per node i: u_i = mean_{j->i} sab_j.x + scd_i.x ;  v_i symmetric
//   out[p] = sigmoid(u[ps] + v[pd] + blin)
// ---------------------------------------------------------------------------

#define NN 50000
#define MAXE 800000

__device__ int   g_deg[NN];
__device__ int   g_off[NN + 1];
__device__ int   g_cur[NN];
__device__ int   g_adj[MAXE];
__device__ __align__(16) float g_y[(size_t)NN * 256];
__device__ __align__(8)  float2 g_sab[NN];
__device__ __align__(8)  float2 g_scd[NN];
__device__ float g_u[NN];
__device__ float g_v[NN];
__device__ __align__(16) float g_avec[128];
__device__ __align__(16) float g_bvec[128];
__device__ __align__(16) float g_cvec[128];
__device__ __align__(16) float g_dvec[128];
__device__ float g_kA, g_kB;

// ------------------------------- CSR build --------------------------------

__global__ void zero_deg_kernel() {
    int i = blockIdx.x * blockDim.x + threadIdx.x;
    if (i < NN) g_deg[i] = 0;
}

__global__ void deg_count_kernel(const int* __restrict__ dst, int E) {
    int stride = gridDim.x * blockDim.x;
    for (int e = blockIdx.x * blockDim.x + threadIdx.x; e < E; e += stride)
        atomicAdd(&g_deg[dst[e]], 1);
}

// single-block exclusive scan of g_deg -> g_off / g_cur (n = NN)
__global__ void scan_kernel(int n) {
    __shared__ int part[1024];
    const int t = threadIdx.x;
    const int C = (NN + 1023) / 1024;   // 49
    int base = t * C;
    int s = 0;
    for (int i = 0; i < C; i++) {
        int idx = base + i;
        if (idx < n) s += g_deg[idx];
    }
    part[t] = s;
    __syncthreads();
    // Hillis-Steele inclusive scan
    for (int off = 1; off < 1024; off <<= 1) {
        int v = (t >= off) ? part[t - off] : 0;
        __syncthreads();
        part[t] += v;
        __syncthreads();
    }
    int ex = (t == 0) ? 0 : part[t - 1];
    for (int i = 0; i < C; i++) {
        int idx = base + i;
        if (idx < n) {
            int d = g_deg[idx];
            g_off[idx] = ex;
            g_cur[idx] = ex;
            ex += d;
        }
    }
    if (t == 0) g_off[n] = part[1023];
}

__global__ void scatter_kernel(const int* __restrict__ src,
                               const int* __restrict__ dst, int E) {
    int stride = gridDim.x * blockDim.x;
    for (int e = blockIdx.x * blockDim.x + threadIdx.x; e < E; e += stride) {
        int d = dst[e];
        int p = atomicAdd(&g_cur[d], 1);
        g_adj[p] = src[e];
    }
}

// --------------------- layer-2 weight collapse (tiny) ---------------------
// avec[j] = sum_k W2l[j,k] * Wlin[k],      bvec[j] = sum_k W2l[j,k] * Wlin[64+k]
// cvec[j] = sum_k W2r[j,k] * Wlin[k],      dvec[j] = sum_k W2r[j,k] * Wlin[64+k]
// kA = b2 . Wlin[0:64],  kB = b2 . Wlin[64:128]
__global__ void prevec_kernel(const float* __restrict__ W2l,
                              const float* __restrict__ W2r,
                              const float* __restrict__ b2,
                              const float* __restrict__ Wlin) {
    int j = threadIdx.x;  // 0..127
    float a = 0.f, b = 0.f, c = 0.f, d = 0.f;
    #pragma unroll 8
    for (int k = 0; k < 64; k++) {
        float wl = W2l[j * 64 + k];
        float wr = W2r[j * 64 + k];
        float wa = Wlin[k];
        float wb = Wlin[64 + k];
        a += wl * wa; b += wl * wb;
        c += wr * wa; d += wr * wb;
    }
    g_avec[j] = a; g_bvec[j] = b; g_cvec[j] = c; g_dvec[j] = d;
    if (j == 0) {
        float ka = 0.f, kb = 0.f;
        for (int k = 0; k < 64; k++) {
            ka += b2[k] * Wlin[k];
            kb += b2[k] * Wlin[64 + k];
        }
        g_kA = ka; g_kB = kb;
    }
}

// ------------------------------ GEMM: y = x @ [W1l|W1r] -------------------
// block tile: 64 rows x 128 cols, 256 threads, thread tile 4x8.
// Ws: 128x128 fp32 (64KB), Xs: transposed x tile, stride 68 (~34KB).
#define XS_STRIDE 68
#define GEMM_SMEM (128 * 128 * 4 + 128 * XS_STRIDE * 4)

__global__ void __launch_bounds__(256, 2)
gemm_kernel(const float* __restrict__ x,
            const float* __restrict__ W1l,
            const float* __restrict__ W1r, int n) {
    extern __shared__ float sm[];
    float* Ws = sm;                    // [128][128]
    float* Xs = sm + 128 * 128;        // [128][XS_STRIDE], Xs[k][r] = x[r0+r][k]

    const int half = blockIdx.x & 1;
    const int r0 = (blockIdx.x >> 1) * 64;
    const float* W = half ? W1r : W1l;
    const int t = threadIdx.x;

    // load W half (16384 floats)
    for (int i = t; i < 4096; i += 256)
        ((float4*)Ws)[i] = ((const float4*)W)[i];

    // load x tile transposed
    {
        int row = t >> 2;                 // 0..63
        int kq0 = (t & 3) * 8;            // float4 col-group base
        int grow = r0 + row;
        const float4* xrow = (const float4*)(x + (size_t)grow * 128);
        #pragma unroll
        for (int i = 0; i < 8; i++) {
            int kq = kq0 + i;             // 0..31
            float4 v = (grow < n) ? xrow[kq] : make_float4(0.f, 0.f, 0.f, 0.f);
            int k = kq * 4;
            Xs[(k + 0) * XS_STRIDE + row] = v.x;
            Xs[(k + 1) * XS_STRIDE + row] = v.y;
            Xs[(k + 2) * XS_STRIDE + row] = v.z;
            Xs[(k + 3) * XS_STRIDE + row] = v.w;
        }
    }
    __syncthreads();

    const int tx = t & 15;    // col group: 8 cols
    const int ty = t >> 4;    // row group: 4 rows
    float acc[4][8];
    #pragma unroll
    for (int i = 0; i < 4; i++)
        #pragma unroll
        for (int j = 0; j < 8; j++) acc[i][j] = 0.f;

    #pragma unroll 16
    for (int k = 0; k < 128; k++) {
        float4 xv = *(const float4*)(Xs + k * XS_STRIDE + ty * 4);
        float4 w0 = *(const float4*)(Ws + k * 128 + tx * 8);
        float4 w1 = *(const float4*)(Ws + k * 128 + tx * 8 + 4);
        float xr[4] = {xv.x, xv.y, xv.z, xv.w};
        float wr[8] = {w0.x, w0.y, w0.z, w0.w, w1.x, w1.y, w1.z, w1.w};
        #pragma unroll
        for (int i = 0; i < 4; i++)
            #pragma unroll
            for (int j = 0; j < 8; j++)
                acc[i][j] += xr[i] * wr[j];
    }

    #pragma unroll
    for (int i = 0; i < 4; i++) {
        int grow = r0 + ty * 4 + i;
        if (grow < n) {
            float* o = g_y + (size_t)grow * 256 + half * 128 + tx * 8;
            *(float4*)(o)     = make_float4(acc[i][0], acc[i][1], acc[i][2], acc[i][3]);
            *(float4*)(o + 4) = make_float4(acc[i][4], acc[i][5], acc[i][6], acc[i][7]);
        }
    }
}

// --------------- layer 1 aggregate + relu + 4 dot products -----------------
// one warp per node; lane covers 4 of the 128 features (float4).
__global__ void __launch_bounds__(256)
layer1_agg_kernel(const float* __restrict__ b1, int n) {
    int warp = (blockIdx.x * blockDim.x + threadIdx.x) >> 5;
    int lane = threadIdx.x & 31;
    if (warp >= n) return;

    int off = g_off[warp];
    int end = g_off[warp + 1];
    int cnt = end - off;

    float4 acc = make_float4(0.f, 0.f, 0.f, 0.f);
    for (int base = off; base < end; base += 32) {
        int m = end - base; if (m > 32) m = 32;
        int jl = (lane < m) ? g_adj[base + lane] : 0;
        #pragma unroll 4
        for (int q = 0; q < m; q++) {
            int j = __shfl_sync(0xffffffffu, jl, q);
            float4 v = ((const float4*)(g_y + (size_t)j * 256))[lane];
            acc.x += v.x; acc.y += v.y; acc.z += v.z; acc.w += v.w;
        }
    }

    float inv = 1.0f / fmaxf((float)cnt, 1.0f);
    float4 r  = ((const float4*)(g_y + (size_t)warp * 256 + 128))[lane];
    float4 bb = ((const float4*)b1)[lane];
    float4 h;
    h.x = fmaxf(acc.x * inv + r.x + bb.x, 0.f);
    h.y = fmaxf(acc.y * inv + r.y + bb.y, 0.f);
    h.z = fmaxf(acc.z * inv + r.z + bb.z, 0.f);
    h.w = fmaxf(acc.w * inv + r.w + bb.w, 0.f);

    float4 av = ((const float4*)g_avec)[lane];
    float4 bv = ((const float4*)g_bvec)[lane];
    float4 cv = ((const float4*)g_cvec)[lane];
    float4 dv = ((const float4*)g_dvec)[lane];
    float pa = h.x * av.x + h.y * av.y + h.z * av.z + h.w * av.w;
    float pb = h.x * bv.x + h.y * bv.y + h.z * bv.z + h.w * bv.w;
    float pc = h.x * cv.x + h.y * cv.y + h.z * cv.z + h.w * cv.w;
    float pd = h.x * dv.x + h.y * dv.y + h.z * dv.z + h.w * dv.w;
    #pragma unroll
    for (int s = 16; s > 0; s >>= 1) {
        pa += __shfl_xor_sync(0xffffffffu, pa, s);
        pb += __shfl_xor_sync(0xffffffffu, pb, s);
        pc += __shfl_xor_sync(0xffffffffu, pc, s);
        pd += __shfl_xor_sync(0xffffffffu, pd, s);
    }
    if (lane == 0) {
        g_sab[warp] = make_float2(pa, pb);
        g_scd[warp] = make_float2(pc + g_kA, pd + g_kB);
    }
}

// ---------------------- layer 2: scalar aggregation ------------------------
__global__ void __launch_bounds__(256)
layer2_agg_kernel(int n) {
    int warp = (blockIdx.x * blockDim.x + threadIdx.x) >> 5;
    int lane = threadIdx.x & 31;
    if (warp >= n) return;

    int off = g_off[warp];
    int end = g_off[warp + 1];
    int cnt = end - off;

    float pa = 0.f, pb = 0.f;
    for (int e = off + lane; e < end; e += 32) {
        int j = g_adj[e];
        float2 s = g_sab[j];
        pa += s.x; pb += s.y;
    }
    #pragma unroll
    for (int s = 16; s > 0; s >>= 1) {
        pa += __shfl_xor_sync(0xffffffffu, pa, s);
        pb += __shfl_xor_sync(0xffffffffu, pb, s);
    }
    if (lane == 0) {
        float inv = 1.0f / fmaxf((float)cnt, 1.0f);
        float2 scd = g_scd[warp];
        g_u[warp] = pa * inv + scd.x;
        g_v[warp] = pb * inv + scd.y;
    }
}

// ------------------------------- pair head ---------------------------------
__global__ void pairs_kernel(const int* __restrict__ ps,
                             const int* __restrict__ pd,
                             const float* __restrict__ blin,
                             float* __restrict__ out, int P) {
    int p = blockIdx.x * blockDim.x + threadIdx.x;
    if (p >= P) return;
    float t = g_u[ps[p]] + g_v[pd[p]] + blin[0];
    out[p] = 1.0f / (1.0f + __expf(-t));
}

// ---------------------------------------------------------------------------

extern "C" void kernel_launch(void* const* d_in, const int* in_sizes, int n_in,
                              void* d_out, int out_size) {
    const float* x    = (const float*)d_in[0];
    const int*   ei   = (const int*)d_in[1];
    const int*   ep   = (const int*)d_in[2];
    const float* W1l  = (const float*)d_in[3];
    const float* b1   = (const float*)d_in[4];
    const float* W1r  = (const float*)d_in[5];
    const float* W2l  = (const float*)d_in[6];
    const float* b2   = (const float*)d_in[7];
    const float* W2r  = (const float*)d_in[8];
    const float* Wlin = (const float*)d_in[9];
    const float* blin = (const float*)d_in[10];
    float* out = (float*)d_out;

    const int E = in_sizes[1] / 2;
    const int P = in_sizes[2] / 2;
    const int n = NN;

    const int* src = ei;
    const int* dst = ei + E;
    const int* ps  = ep;
    const int* pd  = ep + P;

    // gemm needs ~98KB dynamic smem; idempotent, ignore capture-time errors.
    cudaFuncSetAttribute(gemm_kernel,
                         cudaFuncAttributeMaxDynamicSharedMemorySize, GEMM_SMEM);
    cudaGetLastError();  // clear any benign error from the attribute call

    // CSR build
    zero_deg_kernel<<<(NN + 255) / 256, 256>>>();
    deg_count_kernel<<<1184, 256>>>(dst, E);
    scan_kernel<<<1, 1024>>>(n);
    scatter_kernel<<<1184, 256>>>(src, dst, E);

    // collapsed layer-2 weights
    prevec_kernel<<<1, 128>>>(W2l, W2r, b2, Wlin);

    // y = x @ [W1l | W1r]
    int rowTiles = (n + 63) / 64;
    gemm_kernel<<<rowTiles * 2, 256, GEMM_SMEM>>>(x, W1l, W1r, n);

    // fused layer-1 aggregation + relu + layer-2 weight dots
    layer1_agg_kernel<<<(n + 7) / 8, 256>>>(b1, n);

    // layer-2 scalar aggregation
    layer2_agg_kernel<<<(n + 7) / 8, 256>>>(n);

    // pair scoring
    pairs_kernel<<<(P + 255) / 256, 256>>>(ps, pd, blin, out, P);
}

// round 3
// speedup vs baseline: 1.0849x; 1.0849x over previous
#include <cuda_runtime.h>
#include <cuda_bf16.h>
#include <cstdint>

// ---------------------------------------------------------------------------
// SageConv link predictor, restructured:
//   y = x @ [W1l | W1r]          (mma.sync tf32, [N,256] fp32 out)
//   h_i = relu(mean_{j->i} y_j[0:128] + y_i[128:256] + b1)
//   sab_i = (h.avec, h.bvec) ; scd_i = (h.cvec + kA, h.dvec + kB)
//   u_i = mean_j sab_j.x + scd_i.x ; v symmetric
//   out[p] = sigmoid(u[ps] + v[pd] + blin)
// ---------------------------------------------------------------------------

#define NN 50000
#define MAXE 800000

__device__ int   g_deg[NN];
__device__ int   g_off[NN + 1];
__device__ int   g_cur[NN];
__device__ int   g_adj[MAXE];
__device__ __align__(16) float g_y[(size_t)NN * 256];
__device__ __align__(8)  float2 g_sab[NN];
__device__ __align__(8)  float2 g_scd[NN];
__device__ float g_u[NN];
__device__ float g_v[NN];
__device__ __align__(16) float g_avec[128];
__device__ __align__(16) float g_bvec[128];
__device__ __align__(16) float g_cvec[128];
__device__ __align__(16) float g_dvec[128];
__device__ float g_kA, g_kB;

// ------------------------------- CSR build --------------------------------

__global__ void zero_deg_kernel() {
    int i = blockIdx.x * blockDim.x + threadIdx.x;
    if (i < NN) g_deg[i] = 0;
}

__global__ void deg_count_kernel(const int* __restrict__ dst, int E) {
    int stride = gridDim.x * blockDim.x;
    for (int e = blockIdx.x * blockDim.x + threadIdx.x; e < E; e += stride)
        atomicAdd(&g_deg[dst[e]], 1);
}

__global__ void scan_kernel(int n) {
    __shared__ int part[1024];
    const int t = threadIdx.x;
    const int C = (NN + 1023) / 1024;
    int base = t * C;
    int s = 0;
    for (int i = 0; i < C; i++) {
        int idx = base + i;
        if (idx < n) s += g_deg[idx];
    }
    part[t] = s;
    __syncthreads();
    for (int off = 1; off < 1024; off <<= 1) {
        int v = (t >= off) ? part[t - off] : 0;
        __syncthreads();
        part[t] += v;
        __syncthreads();
    }
    int ex = (t == 0) ? 0 : part[t - 1];
    for (int i = 0; i < C; i++) {
        int idx = base + i;
        if (idx < n) {
            int d = g_deg[idx];
            g_off[idx] = ex;
            g_cur[idx] = ex;
            ex += d;
        }
    }
    if (t == 0) g_off[n] = part[1023];
}

__global__ void scatter_kernel(const int* __restrict__ src,
                               const int* __restrict__ dst, int E) {
    int stride = gridDim.x * blockDim.x;
    for (int e = blockIdx.x * blockDim.x + threadIdx.x; e < E; e += stride) {
        int d = dst[e];
        int p = atomicAdd(&g_cur[d], 1);
        g_adj[p] = src[e];
    }
}

// --------------------- layer-2 weight collapse (tiny) ---------------------

__global__ void prevec_kernel(const float* __restrict__ W2l,
                              const float* __restrict__ W2r,
                              const float* __restrict__ b2,
                              const float* __restrict__ Wlin) {
    int j = threadIdx.x;
    float a = 0.f, b = 0.f, c = 0.f, d = 0.f;
    #pragma unroll 8
    for (int k = 0; k < 64; k++) {
        float wl = W2l[j * 64 + k];
        float wr = W2r[j * 64 + k];
        float wa = Wlin[k];
        float wb = Wlin[64 + k];
        a += wl * wa; b += wl * wb;
        c += wr * wa; d += wr * wb;
    }
    g_avec[j] = a; g_bvec[j] = b; g_cvec[j] = c; g_dvec[j] = d;
    if (j == 0) {
        float ka = 0.f, kb = 0.f;
        for (int k = 0; k < 64; k++) {
            ka += b2[k] * Wlin[k];
            kb += b2[k] * Wlin[64 + k];
        }
        g_kA = ka; g_kB = kb;
    }
}

// ------------------ GEMM: y = x @ [W1l|W1r] via mma.sync tf32 --------------
// Block: 128 rows x 128 cols (half selects W1l/W1r), K=128.
// 8 warps in 2(rows) x 4(cols); warp tile 64x32; mma m16n8k8, 16 k-steps.
// Operands are staged into FRAGMENT-ORDER smem so each per-kstep fragment
// fetch is a single conflict-free LDS.128 (A) / LDS.64 (B).
//   Afrag[mt(8)][ks(16)][lane(32)][4]  = 64KB
//   Bfrag[nt(16)][ks(16)][lane(32)][2] = 64KB
#define GEMM_SMEM (131072)

__device__ __forceinline__ void mma_tf32(float* c, const uint32_t* a,
                                         const uint32_t* b) {
    asm volatile(
        "mma.sync.aligned.m16n8k8.row.col.f32.tf32.tf32.f32 "
        "{%0,%1,%2,%3}, {%4,%5,%6,%7}, {%8,%9}, {%0,%1,%2,%3};"
        : "+f"(c[0]), "+f"(c[1]), "+f"(c[2]), "+f"(c[3])
        : "r"(a[0]), "r"(a[1]), "r"(a[2]), "r"(a[3]), "r"(b[0]), "r"(b[1]));
}

__global__ void __launch_bounds__(256, 1)
gemm_tc_kernel(const float* __restrict__ x,
               const float* __restrict__ W1l,
               const float* __restrict__ W1r, int n) {
    extern __shared__ float sm[];
    float* Af = sm;             // 16384 floats
    float* Bf = sm + 16384;     // 16384 floats

    const int t = threadIdx.x;
    const int half = blockIdx.x & 1;
    const int r0 = (blockIdx.x >> 1) * 128;
    const float* W = half ? W1r : W1l;

    // ---- stage A (x tile) in fragment order ----
    // a-frag layout (m16n8k8 tf32): lane = (row%8)*4 + (col%4),
    // slot = (col/4)*2 + ((row%16)/8)
    for (int idx = t; idx < 4096; idx += 256) {
        int row = idx >> 5;
        int q = idx & 31;
        int grow = r0 + row;
        float4 v = (grow < n) ? ((const float4*)(x + (size_t)grow * 128))[q]
                              : make_float4(0.f, 0.f, 0.f, 0.f);
        int mt = row >> 4, rr = row & 15;
        float e[4] = {v.x, v.y, v.z, v.w};
        #pragma unroll
        for (int j = 0; j < 4; j++) {
            int k = q * 4 + j;
            int ks = k >> 3, c = k & 7;
            int lane = ((rr & 7) << 2) | (c & 3);
            int slot = ((c >> 2) << 1) | (rr >> 3);
            Af[(((mt * 16 + ks) * 32) + lane) * 4 + slot] = e[j];
        }
    }
    // ---- stage B (W transposed to col-major frags) ----
    // b-frag: lane = n_local*4 + (k%4), slot = (k%8)/4
    for (int idx = t; idx < 4096; idx += 256) {
        int k = idx >> 5;
        int q = idx & 31;
        float4 w = ((const float4*)(W + (size_t)k * 128))[q];
        int ks = k >> 3, kk = k & 7;
        int slot = kk >> 2;
        float e[4] = {w.x, w.y, w.z, w.w};
        #pragma unroll
        for (int j = 0; j < 4; j++) {
            int nn = q * 4 + j;
            int nt = nn >> 3;
            int lane = ((nn & 7) << 2) | (kk & 3);
            Bf[(((nt * 16 + ks) * 32) + lane) * 2 + slot] = e[j];
        }
    }
    __syncthreads();

    const int w = t >> 5;
    const int lane = t & 31;
    const int wr = w >> 2;      // 0..1
    const int wc = w & 3;       // 0..3

    float acc[4][4][4];
    #pragma unroll
    for (int m = 0; m < 4; m++)
        #pragma unroll
        for (int j = 0; j < 4; j++)
            #pragma unroll
            for (int e = 0; e < 4; e++) acc[m][j][e] = 0.f;

    const uint32_t* Au = (const uint32_t*)Af;
    const uint32_t* Bu = (const uint32_t*)Bf;

    #pragma unroll 4
    for (int ks = 0; ks < 16; ks++) {
        uint32_t a[4][4], b[4][2];
        #pragma unroll
        for (int m = 0; m < 4; m++) {
            const uint32_t* p = Au + ((((wr * 4 + m) * 16 + ks) * 32) + lane) * 4;
            uint4 v = *(const uint4*)p;
            a[m][0] = v.x; a[m][1] = v.y; a[m][2] = v.z; a[m][3] = v.w;
        }
        #pragma unroll
        for (int j = 0; j < 4; j++) {
            const uint32_t* p = Bu + ((((wc * 4 + j) * 16 + ks) * 32) + lane) * 2;
            uint2 v = *(const uint2*)p;
            b[j][0] = v.x; b[j][1] = v.y;
        }
        #pragma unroll
        for (int m = 0; m < 4; m++)
            #pragma unroll
            for (int j = 0; j < 4; j++)
                mma_tf32(acc[m][j], a[m], b[j]);
    }

    // ---- epilogue: c0,c1 at (row, 2c..2c+1); c2,c3 at row+8 ----
    #pragma unroll
    for (int m = 0; m < 4; m++) {
        int row = r0 + wr * 64 + m * 16 + (lane >> 2);
        #pragma unroll
        for (int j = 0; j < 4; j++) {
            int col = half * 128 + wc * 32 + j * 8 + 2 * (lane & 3);
            if (row < n)
                *(float2*)(g_y + (size_t)row * 256 + col) =
                    make_float2(acc[m][j][0], acc[m][j][1]);
            if (row + 8 < n)
                *(float2*)(g_y + (size_t)(row + 8) * 256 + col) =
                    make_float2(acc[m][j][2], acc[m][j][3]);
        }
    }
}

// --------------- layer 1 aggregate + relu + 4 dot products -----------------

__global__ void __launch_bounds__(256)
layer1_agg_kernel(const float* __restrict__ b1, int n) {
    int warp = (blockIdx.x * blockDim.x + threadIdx.x) >> 5;
    int lane = threadIdx.x & 31;
    if (warp >= n) return;

    int off = g_off[warp];
    int end = g_off[warp + 1];
    int cnt = end - off;

    float4 acc = make_float4(0.f, 0.f, 0.f, 0.f);
    for (int base = off; base < end; base += 32) {
        int m = end - base; if (m > 32) m = 32;
        int jl = (lane < m) ? g_adj[base + lane] : 0;
        #pragma unroll 4
        for (int q = 0; q < m; q++) {
            int j = __shfl_sync(0xffffffffu, jl, q);
            float4 v = ((const float4*)(g_y + (size_t)j * 256))[lane];
            acc.x += v.x; acc.y += v.y; acc.z += v.z; acc.w += v.w;
        }
    }

    float inv = 1.0f / fmaxf((float)cnt, 1.0f);
    float4 r  = ((const float4*)(g_y + (size_t)warp * 256 + 128))[lane];
    float4 bb = ((const float4*)b1)[lane];
    float4 h;
    h.x = fmaxf(acc.x * inv + r.x + bb.x, 0.f);
    h.y = fmaxf(acc.y * inv + r.y + bb.y, 0.f);
    h.z = fmaxf(acc.z * inv + r.z + bb.z, 0.f);
    h.w = fmaxf(acc.w * inv + r.w + bb.w, 0.f);

    float4 av = ((const float4*)g_avec)[lane];
    float4 bv = ((const float4*)g_bvec)[lane];
    float4 cv = ((const float4*)g_cvec)[lane];
    float4 dv = ((const float4*)g_dvec)[lane];
    float pa = h.x * av.x + h.y * av.y + h.z * av.z + h.w * av.w;
    float pb = h.x * bv.x + h.y * bv.y + h.z * bv.z + h.w * bv.w;
    float pc = h.x * cv.x + h.y * cv.y + h.z * cv.z + h.w * cv.w;
    float pd = h.x * dv.x + h.y * dv.y + h.z * dv.z + h.w * dv.w;
    #pragma unroll
    for (int s = 16; s > 0; s >>= 1) {
        pa += __shfl_xor_sync(0xffffffffu, pa, s);
        pb += __shfl_xor_sync(0xffffffffu, pb, s);
        pc += __shfl_xor_sync(0xffffffffu, pc, s);
        pd += __shfl_xor_sync(0xffffffffu, pd, s);
    }
    if (lane == 0) {
        g_sab[warp] = make_float2(pa, pb);
        g_scd[warp] = make_float2(pc + g_kA, pd + g_kB);
    }
}

// ---------------------- layer 2: scalar aggregation ------------------------

__global__ void __launch_bounds__(256)
layer2_agg_kernel(int n) {
    int warp = (blockIdx.x * blockDim.x + threadIdx.x) >> 5;
    int lane = threadIdx.x & 31;
    if (warp >= n) return;

    int off = g_off[warp];
    int end = g_off[warp + 1];
    int cnt = end - off;

    float pa = 0.f, pb = 0.f;
    for (int e = off + lane; e < end; e += 32) {
        int j = g_adj[e];
        float2 s = g_sab[j];
        pa += s.x; pb += s.y;
    }
    #pragma unroll
    for (int s = 16; s > 0; s >>= 1) {
        pa += __shfl_xor_sync(0xffffffffu, pa, s);
        pb += __shfl_xor_sync(0xffffffffu, pb, s);
    }
    if (lane == 0) {
        float inv = 1.0f / fmaxf((float)cnt, 1.0f);
        float2 scd = g_scd[warp];
        g_u[warp] = pa * inv + scd.x;
        g_v[warp] = pb * inv + scd.y;
    }
}

// ------------------------------- pair head ---------------------------------

__global__ void pairs_kernel(const int* __restrict__ ps,
                             const int* __restrict__ pd,
                             const float* __restrict__ blin,
                             float* __restrict__ out, int P) {
    int p = blockIdx.x * blockDim.x + threadIdx.x;
    if (p >= P) return;
    float t = g_u[ps[p]] + g_v[pd[p]] + blin[0];
    out[p] = 1.0f / (1.0f + __expf(-t));
}

// ---------------------------------------------------------------------------

extern "C" void kernel_launch(void* const* d_in, const int* in_sizes, int n_in,
                              void* d_out, int out_size) {
    const float* x    = (const float*)d_in[0];
    const int*   ei   = (const int*)d_in[1];
    const int*   ep   = (const int*)d_in[2];
    const float* W1l  = (const float*)d_in[3];
    const float* b1   = (const float*)d_in[4];
    const float* W1r  = (const float*)d_in[5];
    const float* W2l  = (const float*)d_in[6];
    const float* b2   = (const float*)d_in[7];
    const float* W2r  = (const float*)d_in[8];
    const float* Wlin = (const float*)d_in[9];
    const float* blin = (const float*)d_in[10];
    float* out = (float*)d_out;

    const int E = in_sizes[1] / 2;
    const int P = in_sizes[2] / 2;
    const int n = NN;

    const int* src = ei;
    const int* dst = ei + E;
    const int* ps  = ep;
    const int* pd  = ep + P;

    cudaFuncSetAttribute(gemm_tc_kernel,
                         cudaFuncAttributeMaxDynamicSharedMemorySize, GEMM_SMEM);
    cudaGetLastError();

    // CSR build
    zero_deg_kernel<<<(NN + 255) / 256, 256>>>();
    deg_count_kernel<<<1184, 256>>>(dst, E);
    scan_kernel<<<1, 1024>>>(n);
    scatter_kernel<<<1184, 256>>>(src, dst, E);

    // collapsed layer-2 weights
    prevec_kernel<<<1, 128>>>(W2l, W2r, b2, Wlin);

    // y = x @ [W1l | W1r]  (tensor cores via mma.sync tf32)
    int rowTiles = (n + 127) / 128;
    gemm_tc_kernel<<<rowTiles * 2, 256, GEMM_SMEM>>>(x, W1l, W1r, n);

    // fused layer-1 aggregation + relu + layer-2 weight dots
    layer1_agg_kernel<<<(n + 7) / 8, 256>>>(b1, n);

    // layer-2 scalar aggregation
    layer2_agg_kernel<<<(n + 7) / 8, 256>>>(n);

    // pair scoring
    pairs_kernel<<<(P + 255) / 256, 256>>>(ps, pd, blin, out, P);
}

// round 4
// speedup vs baseline: 1.3261x; 1.2223x over previous
#include <cuda_runtime.h>
#include <cuda_bf16.h>
#include <cstdint>

// ---------------------------------------------------------------------------
// SageConv link predictor, restructured:
//   y = x @ [W1l | W1r]          (mma.sync tf32, [N,256] fp32 out)
//   h_i = relu(mean_{j->i} y_j[0:128] + y_i[128:256] + b1)
//   sab_i = (h.avec, h.bvec) ; scd_i = (h.cvec + kA, h.dvec + kB)
//   u_i = mean_j sab_j.x + scd_i.x ; v symmetric
//   out[p] = sigmoid(u[ps] + v[pd] + blin)
// ---------------------------------------------------------------------------

#define NN 50000
#define MAXE 800000

__device__ int   g_deg[NN];
__device__ int   g_off[NN + 1];
__device__ int   g_cur[NN];
__device__ int   g_adj[MAXE];
__device__ __align__(16) float g_y[(size_t)NN * 256];
__device__ __align__(8)  float2 g_sab[NN];
__device__ __align__(8)  float2 g_scd[NN];
__device__ float g_u[NN];
__device__ float g_v[NN];
__device__ __align__(16) float g_avec[128];
__device__ __align__(16) float g_bvec[128];
__device__ __align__(16) float g_cvec[128];
__device__ __align__(16) float g_dvec[128];
__device__ float g_kA, g_kB;

// ------------------------------- CSR build --------------------------------

__global__ void zero_deg_kernel() {
    int i = blockIdx.x * blockDim.x + threadIdx.x;
    if (i < NN) g_deg[i] = 0;
}

__global__ void deg_count_kernel(const int* __restrict__ dst, int E) {
    int stride = gridDim.x * blockDim.x;
    for (int e = blockIdx.x * blockDim.x + threadIdx.x; e < E; e += stride)
        atomicAdd(&g_deg[dst[e]], 1);
}

__global__ void scan_kernel(int n) {
    __shared__ int part[1024];
    const int t = threadIdx.x;
    const int C = (NN + 1023) / 1024;
    int base = t * C;
    int s = 0;
    for (int i = 0; i < C; i++) {
        int idx = base + i;
        if (idx < n) s += g_deg[idx];
    }
    part[t] = s;
    __syncthreads();
    for (int off = 1; off < 1024; off <<= 1) {
        int v = (t >= off) ? part[t - off] : 0;
        __syncthreads();
        part[t] += v;
        __syncthreads();
    }
    int ex = (t == 0) ? 0 : part[t - 1];
    for (int i = 0; i < C; i++) {
        int idx = base + i;
        if (idx < n) {
            int d = g_deg[idx];
            g_off[idx] = ex;
            g_cur[idx] = ex;
            ex += d;
        }
    }
    if (t == 0) g_off[n] = part[1023];
}

__global__ void scatter_kernel(const int* __restrict__ src,
                               const int* __restrict__ dst, int E) {
    int stride = gridDim.x * blockDim.x;
    for (int e = blockIdx.x * blockDim.x + threadIdx.x; e < E; e += stride) {
        int d = dst[e];
        int p = atomicAdd(&g_cur[d], 1);
        g_adj[p] = src[e];
    }
}

// --------------------- layer-2 weight collapse (tiny) ---------------------

__global__ void prevec_kernel(const float* __restrict__ W2l,
                              const float* __restrict__ W2r,
                              const float* __restrict__ b2,
                              const float* __restrict__ Wlin) {
    int j = threadIdx.x;
    float a = 0.f, b = 0.f, c = 0.f, d = 0.f;
    #pragma unroll 8
    for (int k = 0; k < 64; k++) {
        float wl = W2l[j * 64 + k];
        float wr = W2r[j * 64 + k];
        float wa = Wlin[k];
        float wb = Wlin[64 + k];
        a += wl * wa; b += wl * wb;
        c += wr * wa; d += wr * wb;
    }
    g_avec[j] = a; g_bvec[j] = b; g_cvec[j] = c; g_dvec[j] = d;
    if (j == 0) {
        float ka = 0.f, kb = 0.f;
        for (int k = 0; k < 64; k++) {
            ka += b2[k] * Wlin[k];
            kb += b2[k] * Wlin[64 + k];
        }
        g_kA = ka; g_kB = kb;
    }
}

// ------------------ GEMM: y = x @ [W1l|W1r] via mma.sync tf32 --------------
// Block: 128 rows x 128 cols (half selects W1l/W1r), K=128.
// 8 warps in 2(rows) x 4(cols); warp tile 64x32; mma m16n8k8, 16 k-steps.
// Tiles staged PLAIN row-major with stride 132 floats:
//   producer: float4 STS along rows -> coalesced, conflict-free
//   consumer: scalar LDS.32 at row*132+col, (row,col)=(lane>>2,lane&3)
//             -> bank = (4*row+col)%32, all 32 lanes distinct (132 % 32 == 4)
#define XS 132
#define GEMM_SMEM (2 * 128 * XS * 4)

__device__ __forceinline__ void mma_tf32(float* c, const uint32_t* a,
                                         const uint32_t* b) {
    asm volatile(
        "mma.sync.aligned.m16n8k8.row.col.f32.tf32.tf32.f32 "
        "{%0,%1,%2,%3}, {%4,%5,%6,%7}, {%8,%9}, {%0,%1,%2,%3};"
        : "+f"(c[0]), "+f"(c[1]), "+f"(c[2]), "+f"(c[3])
        : "r"(a[0]), "r"(a[1]), "r"(a[2]), "r"(a[3]), "r"(b[0]), "r"(b[1]));
}

__global__ void __launch_bounds__(256, 1)
gemm_tc_kernel(const float* __restrict__ x,
               const float* __restrict__ W1l,
               const float* __restrict__ W1r, int n) {
    extern __shared__ float sm[];
    float* Xs = sm;               // [128][XS]  Xs[row][k] = x[r0+row][k]
    float* Ws = sm + 128 * XS;    // [128][XS]  Ws[k][nn]  = W[k][nn]

    const int t = threadIdx.x;
    const int half = blockIdx.x & 1;
    const int r0 = (blockIdx.x >> 1) * 128;
    const float* W = half ? W1r : W1l;

    // stage both tiles, plain row-major (coalesced, conflict-free)
    for (int idx = t; idx < 4096; idx += 256) {
        int row = idx >> 5;
        int q = idx & 31;
        int grow = r0 + row;
        float4 v = (grow < n) ? ((const float4*)(x + (size_t)grow * 128))[q]
                              : make_float4(0.f, 0.f, 0.f, 0.f);
        *(float4*)(Xs + row * XS + q * 4) = v;
        float4 w = ((const float4*)(W + (size_t)row * 128))[q];
        *(float4*)(Ws + row * XS + q * 4) = w;
    }
    __syncthreads();

    const int w = t >> 5;
    const int lane = t & 31;
    const int wr = w >> 2;      // 0..1
    const int wc = w & 3;       // 0..3

    float acc[4][4][4];
    #pragma unroll
    for (int m = 0; m < 4; m++)
        #pragma unroll
        for (int j = 0; j < 4; j++)
            #pragma unroll
            for (int e = 0; e < 4; e++) acc[m][j][e] = 0.f;

    // fragment base pointers (conflict-free lane mapping)
    const float* Xp = Xs + (wr * 64 + (lane >> 2)) * XS + (lane & 3);
    const float* Bp = Ws + (lane & 3) * XS + wc * 32 + (lane >> 2);

    #pragma unroll 4
    for (int ks = 0; ks < 16; ks++) {
        uint32_t a[4][4], b[4][2];
        #pragma unroll
        for (int m = 0; m < 4; m++) {
            const float* p = Xp + m * 16 * XS + ks * 8;
            a[m][0] = __float_as_uint(p[0]);            // (row,   col)
            a[m][1] = __float_as_uint(p[8 * XS]);       // (row+8, col)
            a[m][2] = __float_as_uint(p[4]);            // (row,   col+4)
            a[m][3] = __float_as_uint(p[8 * XS + 4]);   // (row+8, col+4)
        }
        #pragma unroll
        for (int j = 0; j < 4; j++) {
            const float* p = Bp + ks * 8 * XS + j * 8;
            b[j][0] = __float_as_uint(p[0]);            // (k,   n)
            b[j][1] = __float_as_uint(p[4 * XS]);       // (k+4, n)
        }
        #pragma unroll
        for (int m = 0; m < 4; m++)
            #pragma unroll
            for (int j = 0; j < 4; j++)
                mma_tf32(acc[m][j], a[m], b[j]);
    }

    // epilogue: c0,c1 at (row, 2c..2c+1); c2,c3 at row+8
    #pragma unroll
    for (int m = 0; m < 4; m++) {
        int row = r0 + wr * 64 + m * 16 + (lane >> 2);
        #pragma unroll
        for (int j = 0; j < 4; j++) {
            int col = half * 128 + wc * 32 + j * 8 + 2 * (lane & 3);
            if (row < n)
                *(float2*)(g_y + (size_t)row * 256 + col) =
                    make_float2(acc[m][j][0], acc[m][j][1]);
            if (row + 8 < n)
                *(float2*)(g_y + (size_t)(row + 8) * 256 + col) =
                    make_float2(acc[m][j][2], acc[m][j][3]);
        }
    }
}

// --------------- layer 1 aggregate + relu + 4 dot products -----------------

__global__ void __launch_bounds__(256)
layer1_agg_kernel(const float* __restrict__ b1, int n) {
    int warp = (blockIdx.x * blockDim.x + threadIdx.x) >> 5;
    int lane = threadIdx.x & 31;
    if (warp >= n) return;

    int off = g_off[warp];
    int end = g_off[warp + 1];
    int cnt = end - off;

    float4 acc = make_float4(0.f, 0.f, 0.f, 0.f);
    for (int base = off; base < end; base += 32) {
        int m = end - base; if (m > 32) m = 32;
        int jl = (lane < m) ? g_adj[base + lane] : 0;
        #pragma unroll 4
        for (int q = 0; q < m; q++) {
            int j = __shfl_sync(0xffffffffu, jl, q);
            float4 v = ((const float4*)(g_y + (size_t)j * 256))[lane];
            acc.x += v.x; acc.y += v.y; acc.z += v.z; acc.w += v.w;
        }
    }

    float inv = 1.0f / fmaxf((float)cnt, 1.0f);
    float4 r  = ((const float4*)(g_y + (size_t)warp * 256 + 128))[lane];
    float4 bb = ((const float4*)b1)[lane];
    float4 h;
    h.x = fmaxf(acc.x * inv + r.x + bb.x, 0.f);
    h.y = fmaxf(acc.y * inv + r.y + bb.y, 0.f);
    h.z = fmaxf(acc.z * inv + r.z + bb.z, 0.f);
    h.w = fmaxf(acc.w * inv + r.w + bb.w, 0.f);

    float4 av = ((const float4*)g_avec)[lane];
    float4 bv = ((const float4*)g_bvec)[lane];
    float4 cv = ((const float4*)g_cvec)[lane];
    float4 dv = ((const float4*)g_dvec)[lane];
    float pa = h.x * av.x + h.y * av.y + h.z * av.z + h.w * av.w;
    float pb = h.x * bv.x + h.y * bv.y + h.z * bv.z + h.w * bv.w;
    float pc = h.x * cv.x + h.y * cv.y + h.z * cv.z + h.w * cv.w;
    float pd = h.x * dv.x + h.y * dv.y + h.z * dv.z + h.w * dv.w;
    #pragma unroll
    for (int s = 16; s > 0; s >>= 1) {
        pa += __shfl_xor_sync(0xffffffffu, pa, s);
        pb += __shfl_xor_sync(0xffffffffu, pb, s);
        pc += __shfl_xor_sync(0xffffffffu, pc, s);
        pd += __shfl_xor_sync(0xffffffffu, pd, s);
    }
    if (lane == 0) {
        g_sab[warp] = make_float2(pa, pb);
        g_scd[warp] = make_float2(pc + g_kA, pd + g_kB);
    }
}

// ---------------------- layer 2: scalar aggregation ------------------------

__global__ void __launch_bounds__(256)
layer2_agg_kernel(int n) {
    int warp = (blockIdx.x * blockDim.x + threadIdx.x) >> 5;
    int lane = threadIdx.x & 31;
    if (warp >= n) return;

    int off = g_off[warp];
    int end = g_off[warp + 1];
    int cnt = end - off;

    float pa = 0.f, pb = 0.f;
    for (int e = off + lane; e < end; e += 32) {
        int j = g_adj[e];
        float2 s = g_sab[j];
        pa += s.x; pb += s.y;
    }
    #pragma unroll
    for (int s = 16; s > 0; s >>= 1) {
        pa += __shfl_xor_sync(0xffffffffu, pa, s);
        pb += __shfl_xor_sync(0xffffffffu, pb, s);
    }
    if (lane == 0) {
        float inv = 1.0f / fmaxf((float)cnt, 1.0f);
        float2 scd = g_scd[warp];
        g_u[warp] = pa * inv + scd.x;
        g_v[warp] = pb * inv + scd.y;
    }
}

// ------------------------------- pair head ---------------------------------

__global__ void pairs_kernel(const int* __restrict__ ps,
                             const int* __restrict__ pd,
                             const float* __restrict__ blin,
                             float* __restrict__ out, int P) {
    int p = blockIdx.x * blockDim.x + threadIdx.x;
    if (p >= P) return;
    float t = g_u[ps[p]] + g_v[pd[p]] + blin[0];
    out[p] = 1.0f / (1.0f + __expf(-t));
}

// ---------------------------------------------------------------------------

extern "C" void kernel_launch(void* const* d_in, const int* in_sizes, int n_in,
                              void* d_out, int out_size) {
    const float* x    = (const float*)d_in[0];
    const int*   ei   = (const int*)d_in[1];
    const int*   ep   = (const int*)d_in[2];
    const float* W1l  = (const float*)d_in[3];
    const float* b1   = (const float*)d_in[4];
    const float* W1r  = (const float*)d_in[5];
    const float* W2l  = (const float*)d_in[6];
    const float* b2   = (const float*)d_in[7];
    const float* W2r  = (const float*)d_in[8];
    const float* Wlin = (const float*)d_in[9];
    const float* blin = (const float*)d_in[10];
    float* out = (float*)d_out;

    const int E = in_sizes[1] / 2;
    const int P = in_sizes[2] / 2;
    const int n = NN;

    const int* src = ei;
    const int* dst = ei + E;
    const int* ps  = ep;
    const int* pd  = ep + P;

    cudaFuncSetAttribute(gemm_tc_kernel,
                         cudaFuncAttributeMaxDynamicSharedMemorySize, GEMM_SMEM);
    cudaGetLastError();

    // CSR build
    zero_deg_kernel<<<(NN + 255) / 256, 256>>>();
    deg_count_kernel<<<1184, 256>>>(dst, E);
    scan_kernel<<<1, 1024>>>(n);
    scatter_kernel<<<1184, 256>>>(src, dst, E);

    // collapsed layer-2 weights
    prevec_kernel<<<1, 128>>>(W2l, W2r, b2, Wlin);

    // y = x @ [W1l | W1r]  (tensor cores via mma.sync tf32)
    int rowTiles = (n + 127) / 128;
    gemm_tc_kernel<<<rowTiles * 2, 256, GEMM_SMEM>>>(x, W1l, W1r, n);

    // fused layer-1 aggregation + relu + layer-2 weight dots
    layer1_agg_kernel<<<(n + 7) / 8, 256>>>(b1, n);

    // layer-2 scalar aggregation
    layer2_agg_kernel<<<(n + 7) / 8, 256>>>(n);

    // pair scoring
    pairs_kernel<<<(P + 255) / 256, 256>>>(ps, pd, blin, out, P);
}

// round 5
// speedup vs baseline: 1.4474x; 1.0915x over previous
#include <cuda_runtime.h>
#include <cuda_bf16.h>
#include <cstdint>

// ---------------------------------------------------------------------------
// SageConv link predictor, restructured:
//   y = x @ [W1l | W1r]          (mma.sync tf32, [N,256] fp32 out)
//   h_i = relu(mean_{j->i} y_j[0:128] + y_i[128:256] + b1)
//   sab_i = (h.avec, h.bvec) ; scd_i = (h.cvec + kA, h.dvec + kB)
//   u_i = mean_j sab_j.x + scd_i.x ; v symmetric
//   out[p] = sigmoid(u[ps] + v[pd] + blin)
// ---------------------------------------------------------------------------

#define NN 50000
#define MAXE 800000

__device__ int   g_deg[NN];
__device__ int   g_off[NN + 1];
__device__ int   g_cur[NN];
__device__ int   g_adj[MAXE];
__device__ __align__(16) float g_y[(size_t)NN * 256];
__device__ __align__(8)  float2 g_sab[NN];
__device__ __align__(8)  float2 g_scd[NN];
__device__ float g_u[NN];
__device__ float g_v[NN];
__device__ __align__(16) float g_avec[128];
__device__ __align__(16) float g_bvec[128];
__device__ __align__(16) float g_cvec[128];
__device__ __align__(16) float g_dvec[128];
__device__ float g_kA, g_kB;

// ------------------------------- CSR build --------------------------------

__global__ void zero_deg_kernel() {
    int i = blockIdx.x * blockDim.x + threadIdx.x;
    if (i < NN) g_deg[i] = 0;
}

__global__ void deg_count_kernel(const int* __restrict__ dst, int E) {
    int stride = gridDim.x * blockDim.x;
    for (int e = blockIdx.x * blockDim.x + threadIdx.x; e < E; e += stride)
        atomicAdd(&g_deg[dst[e]], 1);
}

__global__ void scan_kernel(int n) {
    __shared__ int part[1024];
    const int t = threadIdx.x;
    const int C = (NN + 1023) / 1024;
    int base = t * C;
    int s = 0;
    for (int i = 0; i < C; i++) {
        int idx = base + i;
        if (idx < n) s += g_deg[idx];
    }
    part[t] = s;
    __syncthreads();
    for (int off = 1; off < 1024; off <<= 1) {
        int v = (t >= off) ? part[t - off] : 0;
        __syncthreads();
        part[t] += v;
        __syncthreads();
    }
    int ex = (t == 0) ? 0 : part[t - 1];
    for (int i = 0; i < C; i++) {
        int idx = base + i;
        if (idx < n) {
            int d = g_deg[idx];
            g_off[idx] = ex;
            g_cur[idx] = ex;
            ex += d;
        }
    }
    if (t == 0) g_off[n] = part[1023];
}

__global__ void scatter_kernel(const int* __restrict__ src,
                               const int* __restrict__ dst, int E) {
    int stride = gridDim.x * blockDim.x;
    for (int e = blockIdx.x * blockDim.x + threadIdx.x; e < E; e += stride) {
        int d = dst[e];
        int p = atomicAdd(&g_cur[d], 1);
        g_adj[p] = src[e];
    }
}

// --------------------- layer-2 weight collapse (tiny) ---------------------

__global__ void prevec_kernel(const float* __restrict__ W2l,
                              const float* __restrict__ W2r,
                              const float* __restrict__ b2,
                              const float* __restrict__ Wlin) {
    int j = threadIdx.x;
    float a = 0.f, b = 0.f, c = 0.f, d = 0.f;
    #pragma unroll 8
    for (int k = 0; k < 64; k++) {
        float wl = W2l[j * 64 + k];
        float wr = W2r[j * 64 + k];
        float wa = Wlin[k];
        float wb = Wlin[64 + k];
        a += wl * wa; b += wl * wb;
        c += wr * wa; d += wr * wb;
    }
    g_avec[j] = a; g_bvec[j] = b; g_cvec[j] = c; g_dvec[j] = d;
    if (j == 0) {
        float ka = 0.f, kb = 0.f;
        for (int k = 0; k < 64; k++) {
            ka += b2[k] * Wlin[k];
            kb += b2[k] * Wlin[64 + k];
        }
        g_kA = ka; g_kB = kb;
    }
}

// ------------------ GEMM: y = x @ [W1l|W1r] via mma.sync tf32 --------------
// Block: 128 rows x 256 cols (both halves), K=128. 512 threads, 16 warps in
// 2(rows) x 8(cols); warp tile 64x32; mma m16n8k8, 16 k-steps.
// A staged row-major stride 132 (132%32==4): A-frag LDS bank = lane, no
// conflicts. W staged row-major stride 264 (264%32==8): B-frag bank =
// 8*(lane&3) + (lane>>2), a bit-permutation of lane, no conflicts.
#define XS 132
#define WS 264
#define GEMM_SMEM ((128 * XS + 128 * WS) * 4)

__device__ __forceinline__ void mma_tf32(float* c, const uint32_t* a,
                                         const uint32_t* b) {
    asm volatile(
        "mma.sync.aligned.m16n8k8.row.col.f32.tf32.tf32.f32 "
        "{%0,%1,%2,%3}, {%4,%5,%6,%7}, {%8,%9}, {%0,%1,%2,%3};"
        : "+f"(c[0]), "+f"(c[1]), "+f"(c[2]), "+f"(c[3])
        : "r"(a[0]), "r"(a[1]), "r"(a[2]), "r"(a[3]), "r"(b[0]), "r"(b[1]));
}

__global__ void __launch_bounds__(512, 1)
gemm_tc_kernel(const float* __restrict__ x,
               const float* __restrict__ W1l,
               const float* __restrict__ W1r, int n) {
    extern __shared__ float sm[];
    float* Xs = sm;               // [128][XS]  Xs[row][k] = x[r0+row][k]
    float* Wb = sm + 128 * XS;    // [128][WS]  Wb[k][0:128]=W1l[k], [128:256]=W1r[k]

    const int t = threadIdx.x;
    const int r0 = blockIdx.x * 128;

    // stage x tile (once) and both W halves, coalesced float4
    for (int idx = t; idx < 4096; idx += 512) {
        int row = idx >> 5;
        int q = idx & 31;
        int grow = r0 + row;
        float4 v = (grow < n) ? ((const float4*)(x + (size_t)grow * 128))[q]
                              : make_float4(0.f, 0.f, 0.f, 0.f);
        *(float4*)(Xs + row * XS + q * 4) = v;
    }
    for (int idx = t; idx < 8192; idx += 512) {
        int k = idx >> 6;
        int q = idx & 63;       // float4 index across 256 cols
        const float* Wsrc = (q < 32) ? W1l : W1r;
        float4 w = ((const float4*)(Wsrc + (size_t)k * 128))[q & 31];
        *(float4*)(Wb + k * WS + q * 4) = w;
    }
    __syncthreads();

    const int w = t >> 5;
    const int lane = t & 31;
    const int wr = w >> 3;      // 0..1  (row group of 64)
    const int wc = w & 7;       // 0..7  (col group of 32)

    float acc[4][4][4];
    #pragma unroll
    for (int m = 0; m < 4; m++)
        #pragma unroll
        for (int j = 0; j < 4; j++)
            #pragma unroll
            for (int e = 0; e < 4; e++) acc[m][j][e] = 0.f;

    const float* Xp = Xs + (wr * 64 + (lane >> 2)) * XS + (lane & 3);
    const float* Bp = Wb + (lane & 3) * WS + wc * 32 + (lane >> 2);

    #pragma unroll 4
    for (int ks = 0; ks < 16; ks++) {
        uint32_t a[4][4], b[4][2];
        #pragma unroll
        for (int m = 0; m < 4; m++) {
            const float* p = Xp + m * 16 * XS + ks * 8;
            a[m][0] = __float_as_uint(p[0]);            // (row,   k)
            a[m][1] = __float_as_uint(p[8 * XS]);       // (row+8, k)
            a[m][2] = __float_as_uint(p[4]);            // (row,   k+4)
            a[m][3] = __float_as_uint(p[8 * XS + 4]);   // (row+8, k+4)
        }
        #pragma unroll
        for (int j = 0; j < 4; j++) {
            const float* p = Bp + ks * 8 * WS + j * 8;
            b[j][0] = __float_as_uint(p[0]);            // (k,   nn)
            b[j][1] = __float_as_uint(p[4 * WS]);       // (k+4, nn)
        }
        #pragma unroll
        for (int m = 0; m < 4; m++)
            #pragma unroll
            for (int j = 0; j < 4; j++)
                mma_tf32(acc[m][j], a[m], b[j]);
    }

    // epilogue: c0,c1 at (row, col..col+1); c2,c3 at row+8
    #pragma unroll
    for (int m = 0; m < 4; m++) {
        int row = r0 + wr * 64 + m * 16 + (lane >> 2);
        #pragma unroll
        for (int j = 0; j < 4; j++) {
            int col = wc * 32 + j * 8 + 2 * (lane & 3);
            if (row < n)
                *(float2*)(g_y + (size_t)row * 256 + col) =
                    make_float2(acc[m][j][0], acc[m][j][1]);
            if (row + 8 < n)
                *(float2*)(g_y + (size_t)(row + 8) * 256 + col) =
                    make_float2(acc[m][j][2], acc[m][j][3]);
        }
    }
}

// --------------- layer 1 aggregate + relu + 4 dot products -----------------

__global__ void __launch_bounds__(256)
layer1_agg_kernel(const float* __restrict__ b1, int n) {
    int warp = (blockIdx.x * blockDim.x + threadIdx.x) >> 5;
    int lane = threadIdx.x & 31;
    if (warp >= n) return;

    int off = g_off[warp];
    int end = g_off[warp + 1];
    int cnt = end - off;

    float4 acc = make_float4(0.f, 0.f, 0.f, 0.f);
    for (int base = off; base < end; base += 32) {
        int m = end - base; if (m > 32) m = 32;
        int jl = (lane < m) ? g_adj[base + lane] : 0;
        #pragma unroll 4
        for (int q = 0; q < m; q++) {
            int j = __shfl_sync(0xffffffffu, jl, q);
            float4 v = ((const float4*)(g_y + (size_t)j * 256))[lane];
            acc.x += v.x; acc.y += v.y; acc.z += v.z; acc.w += v.w;
        }
    }

    float inv = 1.0f / fmaxf((float)cnt, 1.0f);
    float4 r  = ((const float4*)(g_y + (size_t)warp * 256 + 128))[lane];
    float4 bb = ((const float4*)b1)[lane];
    float4 h;
    h.x = fmaxf(acc.x * inv + r.x + bb.x, 0.f);
    h.y = fmaxf(acc.y * inv + r.y + bb.y, 0.f);
    h.z = fmaxf(acc.z * inv + r.z + bb.z, 0.f);
    h.w = fmaxf(acc.w * inv + r.w + bb.w, 0.f);

    float4 av = ((const float4*)g_avec)[lane];
    float4 bv = ((const float4*)g_bvec)[lane];
    float4 cv = ((const float4*)g_cvec)[lane];
    float4 dv = ((const float4*)g_dvec)[lane];
    float pa = h.x * av.x + h.y * av.y + h.z * av.z + h.w * av.w;
    float pb = h.x * bv.x + h.y * bv.y + h.z * bv.z + h.w * bv.w;
    float pc = h.x * cv.x + h.y * cv.y + h.z * cv.z + h.w * cv.w;
    float pd = h.x * dv.x + h.y * dv.y + h.z * dv.z + h.w * dv.w;
    #pragma unroll
    for (int s = 16; s > 0; s >>= 1) {
        pa += __shfl_xor_sync(0xffffffffu, pa, s);
        pb += __shfl_xor_sync(0xffffffffu, pb, s);
        pc += __shfl_xor_sync(0xffffffffu, pc, s);
        pd += __shfl_xor_sync(0xffffffffu, pd, s);
    }
    if (lane == 0) {
        g_sab[warp] = make_float2(pa, pb);
        g_scd[warp] = make_float2(pc + g_kA, pd + g_kB);
    }
}

// ---------------------- layer 2: scalar aggregation ------------------------

__global__ void __launch_bounds__(256)
layer2_agg_kernel(int n) {
    int warp = (blockIdx.x * blockDim.x + threadIdx.x) >> 5;
    int lane = threadIdx.x & 31;
    if (warp >= n) return;

    int off = g_off[warp];
    int end = g_off[warp + 1];
    int cnt = end - off;

    float pa = 0.f, pb = 0.f;
    for (int e = off + lane; e < end; e += 32) {
        int j = g_adj[e];
        float2 s = g_sab[j];
        pa += s.x; pb += s.y;
    }
    #pragma unroll
    for (int s = 16; s > 0; s >>= 1) {
        pa += __shfl_xor_sync(0xffffffffu, pa, s);
        pb += __shfl_xor_sync(0xffffffffu, pb, s);
    }
    if (lane == 0) {
        float inv = 1.0f / fmaxf((float)cnt, 1.0f);
        float2 scd = g_scd[warp];
        g_u[warp] = pa * inv + scd.x;
        g_v[warp] = pb * inv + scd.y;
    }
}

// ------------------------------- pair head ---------------------------------

__global__ void pairs_kernel(const int* __restrict__ ps,
                             const int* __restrict__ pd,
                             const float* __restrict__ blin,
                             float* __restrict__ out, int P) {
    int p = blockIdx.x * blockDim.x + threadIdx.x;
    if (p >= P) return;
    float t = g_u[ps[p]] + g_v[pd[p]] + blin[0];
    out[p] = 1.0f / (1.0f + __expf(-t));
}

// ---------------------------------------------------------------------------

extern "C" void kernel_launch(void* const* d_in, const int* in_sizes, int n_in,
                              void* d_out, int out_size) {
    const float* x    = (const float*)d_in[0];
    const int*   ei   = (const int*)d_in[1];
    const int*   ep   = (const int*)d_in[2];
    const float* W1l  = (const float*)d_in[3];
    const float* b1   = (const float*)d_in[4];
    const float* W1r  = (const float*)d_in[5];
    const float* W2l  = (const float*)d_in[6];
    const float* b2   = (const float*)d_in[7];
    const float* W2r  = (const float*)d_in[8];
    const float* Wlin = (const float*)d_in[9];
    const float* blin = (const float*)d_in[10];
    float* out = (float*)d_out;

    const int E = in_sizes[1] / 2;
    const int P = in_sizes[2] / 2;
    const int n = NN;

    const int* src = ei;
    const int* dst = ei + E;
    const int* ps  = ep;
    const int* pd  = ep + P;

    cudaFuncSetAttribute(gemm_tc_kernel,
                         cudaFuncAttributeMaxDynamicSharedMemorySize, GEMM_SMEM);
    cudaGetLastError();

    // CSR build (gemm slotted between scan and scatter so ncu profiles it)
    zero_deg_kernel<<<(NN + 255) / 256, 256>>>();
    deg_count_kernel<<<1184, 256>>>(dst, E);
    scan_kernel<<<1, 1024>>>(n);

    // y = x @ [W1l | W1r]  (tensor cores via mma.sync tf32)
    int rowTiles = (n + 127) / 128;
    gemm_tc_kernel<<<rowTiles, 512, GEMM_SMEM>>>(x, W1l, W1r, n);

    scatter_kernel<<<1184, 256>>>(src, dst, E);

    // collapsed layer-2 weights
    prevec_kernel<<<1, 128>>>(W2l, W2r, b2, Wlin);

    // fused layer-1 aggregation + relu + layer-2 weight dots
    layer1_agg_kernel<<<(n + 7) / 8, 256>>>(b1, n);

    // layer-2 scalar aggregation
    layer2_agg_kernel<<<(n + 7) / 8, 256>>>(n);

    // pair scoring
    pairs_kernel<<<(P + 255) / 256, 256>>>(ps, pd, blin, out, P);
}